// round 14
// baseline (speedup 1.0000x reference)
#include <cuda_runtime.h>
#include <cuda_fp16.h>

namespace {
constexpr int B = 2, H = 128, W = 256, MD = 34, LD = 32;
constexpr int NH = 4, SH = 64, K = 25, P = 7, R = 3;
constexpr int FF1 = 512, FF2 = 256;
constexpr int PP = P * P; // 49
constexpr long M_PIX = (long)B * H * W; // 65536

// ---------------- disco config ----------------
constexpr int TW   = 32;
constexpr int PIX  = 8;
constexpr int NGRP = TW / PIX;
constexpr int TAD  = 256;           // 8 warps, 2 m16-tiles per warp
constexpr int XCOLS = TW + 2 * R;   // 38

constexpr int WEFFH_U2 = 8 * 4 * 32;        // 1024 uint2 per latitude (8 KB)
constexpr int HW1H_U2  = 4 * 4 * 4 * 32;    // 2048 uint2 (16 KB)
constexpr int FW1B_F  = 64 * 5 * 32 * 2;     // 20480 (k padded 34->40)
constexpr int FW2B_F  = 16 * 32 * 4 * 32 * 2;// 131072
constexpr int FW3B_F  = 4 * 32 * 32 * 2;     // 8192

// disco smem (floats): sx (raw fp32) + small vectors
constexpr int OFF_SX   = 0;                         // 8512
constexpr int OFF_SDB  = OFF_SX + LD * P * XCOLS;   // 64
constexpr int OFF_HB1  = OFF_SDB + SH;              // 128
constexpr int OFF_HW2  = OFF_HB1 + NH * 32;         // 128
constexpr int OFF_HB2  = OFF_HW2 + NH * 32;         // 4
constexpr int SMEM_D_F = OFF_HB2 + NH;              // 8836 fl = 34.6 KB

__device__ __forceinline__ float gelu_exact(float v) {
    return 0.5f * v * (1.0f + erff(v * 0.70710678118654752440f));
}

__device__ __forceinline__ float f2tf_f(float f) {
    unsigned u;
    asm("cvt.rna.tf32.f32 %0, %1;" : "=r"(u) : "f"(f));
    return __uint_as_float(u);
}

// pack two fp32 -> f16x2 register: lo in low 16 bits, hi in high 16 bits
__device__ __forceinline__ unsigned packh2(float lo, float hi) {
    unsigned d;
    asm("cvt.rn.f16x2.f32 %0, %1, %2;" : "=r"(d) : "f"(hi), "f"(lo));
    return d;
}

__device__ __forceinline__ void mma_tf32(float c[4], const float4& a, const float2& b) {
    const unsigned* A = reinterpret_cast<const unsigned*>(&a);
    const unsigned* Bv = reinterpret_cast<const unsigned*>(&b);
    asm volatile(
        "mma.sync.aligned.m16n8k8.row.col.f32.tf32.tf32.f32 "
        "{%0,%1,%2,%3},{%4,%5,%6,%7},{%8,%9},{%0,%1,%2,%3};\n"
        : "+f"(c[0]), "+f"(c[1]), "+f"(c[2]), "+f"(c[3])
        : "r"(A[0]), "r"(A[1]), "r"(A[2]), "r"(A[3]), "r"(Bv[0]), "r"(Bv[1]));
}

__device__ __forceinline__ void mma_f16(float c[4], unsigned a0, unsigned a1,
                                        unsigned a2, unsigned a3,
                                        unsigned b0, unsigned b1) {
    asm volatile(
        "mma.sync.aligned.m16n8k16.row.col.f32.f16.f16.f32 "
        "{%0,%1,%2,%3},{%4,%5,%6,%7},{%8,%9},{%0,%1,%2,%3};\n"
        : "+f"(c[0]), "+f"(c[1]), "+f"(c[2]), "+f"(c[3])
        : "r"(a0), "r"(a1), "r"(a2), "r"(a3), "r"(b0), "r"(b1));
}
} // namespace

// device-global scratch (no runtime allocation)
__device__ __align__(16) uint2 g_weffBh[H * WEFFH_U2]; // fp16 B-frags per lat
__device__ __align__(16) uint2 g_hw1h[HW1H_U2];        // fp16 B-frags
__device__ __align__(16) float g_fw1B[FW1B_F];
__device__ __align__(16) float g_fw2B[FW2B_F];
__device__ __align__(16) float g_fw3B[FW3B_F];

// =====================================================================
// prep: fold psi into disco_w per latitude -> fp16 k16 B-frags
//   idx = (nt*4+ks)*32+lane ; b0 = {w[p0][s], w[p0+1][s]}, b1 = {+8,+9}
// =====================================================================
__global__ void prep_weffBh(const float* __restrict__ dw,
                            const float* __restrict__ psi) {
    const int h = blockIdx.x;
    for (int e = threadIdx.x; e < WEFFH_U2; e += blockDim.x) {
        int lane = e & 31; int t = e >> 5;
        int ks = t & 3, nt = t >> 2;
        int g = lane >> 2, tg = lane & 3;
        int s = nt * 8 + g;
        int p0 = ks * 16 + 2 * tg;
        float wv[4];
        #pragma unroll
        for (int j = 0; j < 4; j++) {
            int p = p0 + (j >> 1) * 8 + (j & 1);
            float acc = 0.f;
            if (p < PP) {
                #pragma unroll
                for (int k = 0; k < K; k++)
                    acc += dw[s * K + k] * psi[(k * H + h) * PP + p];
            }
            wv[j] = acc;
        }
        uint2 o;
        o.x = packh2(wv[0], wv[1]);
        o.y = packh2(wv[2], wv[3]);
        g_weffBh[h * WEFFH_U2 + e] = o;
    }
}

// =====================================================================
// prep: hw1 -> fp16 k16 B-frags: idx = ((n*4+nt2)*4+ks)*32+lane
//   b0 = {hw1[n][s0][o], hw1[n][s0+1][o]}, b1 = {s0+8, s0+9}
// =====================================================================
__global__ void prep_hw1h(const float* __restrict__ hw1) {
    int e = blockIdx.x * blockDim.x + threadIdx.x;
    if (e >= HW1H_U2) return;
    int lane = e & 31; int t = e >> 5;
    int ks = t & 3; t >>= 2;
    int nt2 = t & 3; int n = t >> 2;
    int g = lane >> 2, tg = lane & 3;
    int o = nt2 * 8 + g;
    int s0 = ks * 16 + 2 * tg;
    uint2 out;
    out.x = packh2(hw1[(n * SH + s0) * 32 + o],     hw1[(n * SH + s0 + 1) * 32 + o]);
    out.y = packh2(hw1[(n * SH + s0 + 8) * 32 + o], hw1[(n * SH + s0 + 9) * 32 + o]);
    g_hw1h[e] = out;
}

// =====================================================================
// prep: fw1 / fw3 into tf32 B-frag layouts (FFN unchanged)
// =====================================================================
__global__ void prep_small(const float* __restrict__ fw1,
                           const float* __restrict__ fw3) {
    int e = blockIdx.x * blockDim.x + threadIdx.x;
    if (e < FW1B_F) {
        int half = e & 1, t = e >> 1;
        int lane = t & 31; t >>= 5;
        int ks = t % 5, nt = t / 5;
        int g = lane >> 2, tg = lane & 3;
        int k = ks * 8 + tg + 4 * half;
        int n = nt * 8 + g;
        g_fw1B[e] = (k < MD) ? f2tf_f(fw1[k * FF1 + n]) : 0.f;
        return;
    }
    e -= FW1B_F;
    if (e < FW3B_F) {
        int half = e & 1, t = e >> 1;
        int lane = t & 31; t >>= 5;
        int ks = t & 31, nt = t >> 5;
        int g = lane >> 2, tg = lane & 3;
        int k = ks * 8 + tg + 4 * half;
        int n = nt * 8 + g;
        g_fw3B[e] = f2tf_f(fw3[k * LD + n]);
    }
}

// =====================================================================
// prep: fw2 into per-chunk tf32 B-frag layout
// =====================================================================
__global__ void prep_fw2B(const float* __restrict__ fw2) {
    int e = blockIdx.x * blockDim.x + threadIdx.x;
    if (e >= FW2B_F) return;
    int kc = e >> 13, r = e & 8191;
    int half = r & 1; r >>= 1;
    int lane = r & 31; r >>= 5;
    int ks = r & 3; int nt = r >> 2;
    int g = lane >> 2, tg = lane & 3;
    int k = kc * 32 + ks * 8 + tg + 4 * half;
    int n = nt * 8 + g;
    g_fw2B[e] = f2tf_f(fw2[k * FF2 + n]);
}

// =====================================================================
// disco conv + head MLP + residual — fp16 m16n8k16.
// 8 warps x 2 m16-tiles; C-frag of phase 1 IS the A-frag of phase 2
// (pack-cvt only, no shuffles, no smem round trip).
// =====================================================================
__global__ __launch_bounds__(TAD, 2) void disco_head_mma(
    const float* __restrict__ x,   const float* __restrict__ db,
    const float* __restrict__ hb1, const float* __restrict__ hw2,
    const float* __restrict__ hb2, float* __restrict__ out)
{
    extern __shared__ float sm[];
    float* sx   = sm + OFF_SX;
    float* sdb  = sm + OFF_SDB;
    float* shb1 = sm + OFF_HB1;
    float* shw2 = sm + OFF_HW2;
    float* shb2 = sm + OFF_HB2;

    const int tid = threadIdx.x;
    const int lane = tid & 31, mt = tid >> 5;   // mt 0..7
    const int g  = lane >> 2, tg = lane & 3;
    const int w0 = blockIdx.x * TW;
    const int h  = blockIdx.y;
    const int b  = blockIdx.z;

    if (tid < SH) sdb[tid] = db[tid];
    if (tid < NH * 32) { shb1[tid] = hb1[tid]; shw2[tid] = hw2[tid]; }
    if (tid < NH) shb2[tid] = hb2[tid];

    // stencil tile: raw fp32 (fp16 rounding happens at pack time)
    for (int i = tid; i < LD * P * XCOLS; i += TAD) {
        int ld = i & 31; int pos = i >> 5;
        int r = pos / XCOLS, c = pos % XCOLS;
        int lat = h + r - R; lat = lat < 0 ? 0 : (lat > H - 1 ? H - 1 : lat);
        int lon = (w0 + c - R + W) & (W - 1);
        sx[(ld * P + r) * XCOLS + c] = x[((b * H + lat) * W + lon) * MD + ld];
    }
    for (int i = tid; i < TW * 2; i += TAD) {
        int px = i >> 1, j = i & 1;
        int gi = ((b * H + h) * W + (w0 + px)) * MD + LD + j;
        out[gi] = x[gi];
    }
    __syncthreads();

    const int nh  = mt >> 1;
    const int ldA = nh * 8 + 4 * (mt & 1);
    const int px  = g;
    const int base0 = (ldA + 0) * P * XCOLS;
    const int base1 = (ldA + 1) * P * XCOLS;
    const int base2 = (ldA + 2) * P * XCOLS;
    const int base3 = (ldA + 3) * P * XCOLS;

    // tap offsets per k16 step: {p0, p0+1, p0+8, p0+9}; p>=49 -> offset 0
    // (corresponding weight fragment is zero, so the value is ignored)
    int t00[4], t01[4], t10[4], t11[4];
    #pragma unroll
    for (int ks = 0; ks < 4; ks++) {
        int p = ks * 16 + 2 * tg;
        t00[ks] = (p     < PP) ? ((p)     / 7) * XCOLS + (p)     % 7 : 0;
        t01[ks] = (p + 1 < PP) ? ((p + 1) / 7) * XCOLS + (p + 1) % 7 : 0;
        t10[ks] = (p + 8 < PP) ? ((p + 8) / 7) * XCOLS + (p + 8) % 7 : 0;
        t11[ks] = (p + 9 < PP) ? ((p + 9) / 7) * XCOLS + (p + 9) % 7 : 0;
    }

    const uint2* wbh  = g_weffBh + (long)h * WEFFH_U2;
    const uint2* h1h  = g_hw1h;

    for (int grp = 0; grp < NGRP; grp++) {
        const int cbase = grp * PIX + px;
        const int cb0 = base0 + cbase, cb1 = base1 + cbase;
        const int cb2 = base2 + cbase, cb3 = base3 + cbase;

        // phase 1: d = taps @ weff  (two m16 tiles, N=64, K=64 fp16)
        float c1[2][8][4] = {};
        #pragma unroll
        for (int ks = 0; ks < 4; ks++) {
            const unsigned a0t0 = packh2(sx[cb0 + t00[ks]], sx[cb0 + t01[ks]]);
            const unsigned a1t0 = packh2(sx[cb1 + t00[ks]], sx[cb1 + t01[ks]]);
            const unsigned a2t0 = packh2(sx[cb0 + t10[ks]], sx[cb0 + t11[ks]]);
            const unsigned a3t0 = packh2(sx[cb1 + t10[ks]], sx[cb1 + t11[ks]]);
            const unsigned a0t1 = packh2(sx[cb2 + t00[ks]], sx[cb2 + t01[ks]]);
            const unsigned a1t1 = packh2(sx[cb3 + t00[ks]], sx[cb3 + t01[ks]]);
            const unsigned a2t1 = packh2(sx[cb2 + t10[ks]], sx[cb2 + t11[ks]]);
            const unsigned a3t1 = packh2(sx[cb3 + t10[ks]], sx[cb3 + t11[ks]]);
            #pragma unroll
            for (int nt = 0; nt < 8; nt++) {
                const uint2 bb = __ldg(&wbh[(nt * 4 + ks) * 32 + lane]);
                mma_f16(c1[0][nt], a0t0, a1t0, a2t0, a3t0, bb.x, bb.y);
                mma_f16(c1[1][nt], a0t1, a1t1, a2t1, a3t1, bb.x, bb.y);
            }
        }

        // phase 2: h = d @ hw1[head]  (K=64 fp16; C-frag == A-frag layout)
        float c2[2][4][4] = {};
        #pragma unroll
        for (int ks = 0; ks < 4; ks++) {
            const int sA = ks * 16 + 2 * tg;
            const float bA0 = sdb[sA], bA1 = sdb[sA + 1];
            const float bB0 = sdb[sA + 8], bB1 = sdb[sA + 9];
            unsigned af[2][4];
            #pragma unroll
            for (int t = 0; t < 2; t++) {
                af[t][0] = packh2(c1[t][2 * ks][0] + bA0, c1[t][2 * ks][1] + bA1);
                af[t][1] = packh2(c1[t][2 * ks][2] + bA0, c1[t][2 * ks][3] + bA1);
                af[t][2] = packh2(c1[t][2 * ks + 1][0] + bB0, c1[t][2 * ks + 1][1] + bB1);
                af[t][3] = packh2(c1[t][2 * ks + 1][2] + bB0, c1[t][2 * ks + 1][3] + bB1);
            }
            #pragma unroll
            for (int nt2 = 0; nt2 < 4; nt2++) {
                const uint2 bb = __ldg(&h1h[((nh * 4 + nt2) * 4 + ks) * 32 + lane]);
                mma_f16(c2[0][nt2], af[0][0], af[0][1], af[0][2], af[0][3], bb.x, bb.y);
                mma_f16(c2[1][nt2], af[1][0], af[1][1], af[1][2], af[1][3], bb.x, bb.y);
            }
        }

        // epilogue: gelu + hw2 dot + lane reduce + residual (fp32 path)
        #pragma unroll
        for (int t = 0; t < 2; t++) {
            float part0 = 0.f, part1 = 0.f;
            #pragma unroll
            for (int nt2 = 0; nt2 < 4; nt2++) {
                const int o0 = nt2 * 8 + 2 * tg, o1 = o0 + 1;
                const float w0v = shw2[nh * 32 + o0], w1v = shw2[nh * 32 + o1];
                const float bb0 = shb1[nh * 32 + o0], bb1 = shb1[nh * 32 + o1];
                part0 += gelu_exact(c2[t][nt2][0] + bb0) * w0v
                       + gelu_exact(c2[t][nt2][1] + bb1) * w1v;
                part1 += gelu_exact(c2[t][nt2][2] + bb0) * w0v
                       + gelu_exact(c2[t][nt2][3] + bb1) * w1v;
            }
            part0 += __shfl_xor_sync(0xffffffffu, part0, 1);
            part0 += __shfl_xor_sync(0xffffffffu, part0, 2);
            part1 += __shfl_xor_sync(0xffffffffu, part1, 1);
            part1 += __shfl_xor_sync(0xffffffffu, part1, 2);
            if (tg == 0) {
                const int ld0 = ldA + 2 * t, ld1 = ld0 + 1;
                const int pxg = grp * PIX + px;
                const float v0 = part0 + shb2[nh]
                               + sx[(ld0 * P + R) * XCOLS + pxg + R];
                const float v1 = part1 + shb2[nh]
                               + sx[(ld1 * P + R) * XCOLS + pxg + R];
                const long o = ((long)(b * H + h) * W + w0 + pxg) * MD;
                out[o + ld0] = v0;
                out[o + ld1] = v1;
            }
        }
    }
}

// =====================================================================
// FFN fully fused (tf32, unchanged from R13): t1 chunks computed on the
// fly, exchanged via smem into stage-2 A-frags; t2 in smem; fw3 + residual.
// =====================================================================
namespace {
constexpr int FB_BUF  = 10240;                 // 2048 t1c + 8192 fw2
constexpr int FST2_F  = 4 * 32 * 32 * 4;       // 16384
constexpr int FSF3    = FST2_F;                // sf3 offset
constexpr int FFB1    = 24576;                 // fb1 offset
constexpr int SFN_F   = FFB1 + FF1;            // 25088 floats = 100.4 KB
}
__global__ __launch_bounds__(512) void ffn_fused(
    const float* __restrict__ xin, const float* __restrict__ fb1,
    const float* __restrict__ fb2, const float* __restrict__ fb3,
    float* __restrict__ out)
{
    extern __shared__ float sm[];
    float* sfb1 = sm + FFB1;
    const int tid = threadIdx.x, lane = tid & 31, w = tid >> 5;
    const int mw = w >> 2, nw = w & 3;
    const int g = lane >> 2, tg = lane & 3;
    const long r0 = (long)blockIdx.x * 64;

    sfb1[tid] = fb1[tid];

    {
        const int r = tid >> 3, rr7 = r & 7, rhi = (r >> 3) & 1, mt = r >> 4;
        const int kb = (tid & 7) * 5;
        #pragma unroll
        for (int j = 0; j < 5; j++) {
            const int k = kb + j;
            const float v = (k < MD) ? f2tf_f(xin[(r0 + r) * MD + k]) : 0.f;
            sm[((mt * 5 + (k >> 3)) * 32 + rr7 * 4 + (k & 3)) * 4
               + rhi + (((k >> 2) & 1) << 1)] = v;
        }
    }
    __syncthreads();
    float4 xfrag[5];
    #pragma unroll
    for (int ks = 0; ks < 5; ks++)
        xfrag[ks] = reinterpret_cast<const float4*>(sm)[(mw * 5 + ks) * 32 + lane];
    __syncthreads();

    float c2[8][4] = {};
    const float2* fw1b2 = reinterpret_cast<const float2*>(g_fw1B);
    const float4* fw2v4 = reinterpret_cast<const float4*>(g_fw2B);

    for (int kc = 0; kc < 16; kc++) {
        float* buf  = sm + (kc & 1) * FB_BUF;
        float* st1c = buf;
        float* sB   = buf + 2048;

        {
            float4* dst = reinterpret_cast<float4*>(sB);
            #pragma unroll
            for (int i = 0; i < 4; i++)
                dst[tid + i * 512] = fw2v4[kc * 2048 + tid + i * 512];
        }

        float c1[4] = {};
        #pragma unroll
        for (int ks = 0; ks < 5; ks++) {
            float2 bb = __ldg(&fw1b2[(((kc * 4 + nw) * 5) + ks) * 32 + lane]);
            mma_tf32(c1, xfrag[ks], bb);
        }
        {
            const int n = kc * 32 + nw * 8 + 2 * tg;
            const float b0 = sfb1[n], b1 = sfb1[n + 1];
            const int kk0 = 2 * tg, kk1 = kk0 + 1;
            const int i0 = mw * 512 + (nw * 32 + g * 4 + (kk0 & 3)) * 4 + ((kk0 >> 2) << 1);
            const int i1 = mw * 512 + (nw * 32 + g * 4 + (kk1 & 3)) * 4 + ((kk1 >> 2) << 1);
            *reinterpret_cast<float2*>(st1c + i0) =
                make_float2(f2tf_f(gelu_exact(c1[0] + b0)),
                            f2tf_f(gelu_exact(c1[2] + b0)));
            *reinterpret_cast<float2*>(st1c + i1) =
                make_float2(f2tf_f(gelu_exact(c1[1] + b1)),
                            f2tf_f(gelu_exact(c1[3] + b1)));
        }
        __syncthreads();

        #pragma unroll
        for (int ks = 0; ks < 4; ks++) {
            float4 a = reinterpret_cast<const float4*>(st1c)[(mw * 4 + ks) * 32 + lane];
            #pragma unroll
            for (int ni = 0; ni < 8; ni++) {
                float2 bb = reinterpret_cast<const float2*>(sB)[((nw * 8 + ni) * 4 + ks) * 32 + lane];
                mma_tf32(c2[ni], a, bb);
            }
        }
    }
    __syncthreads();

    float* sT2 = sm;
    float* sf3 = sm + FSF3;
    {
        const float4* src = reinterpret_cast<const float4*>(g_fw3B);
        float4* dst = reinterpret_cast<float4*>(sf3);
        #pragma unroll
        for (int i = 0; i < 4; i++) dst[tid + i * 512] = src[tid + i * 512];
    }
    float2* sT2v2 = reinterpret_cast<float2*>(sT2);
    #pragma unroll
    for (int ni = 0; ni < 8; ni++) {
        const int nt = nw * 8 + ni;
        const int n2 = nt * 8 + 2 * tg;
        const int kk0 = n2 & 7, kk1 = kk0 + 1;
        const int base = (mw * 32 + nt) * 32;
        const int rgA = ((kk0 >> 2) & 1) << 1;
        const int i0 = (base + g * 4 + (kk0 & 3)) * 4 + rgA;
        const int i1 = (base + g * 4 + (kk1 & 3)) * 4 + rgA;
        const float b0 = fb2[n2], b1 = fb2[n2 + 1];
        sT2v2[i0 >> 1] = make_float2(f2tf_f(gelu_exact(c2[ni][0] + b0)),
                                     f2tf_f(gelu_exact(c2[ni][2] + b0)));
        sT2v2[i1 >> 1] = make_float2(f2tf_f(gelu_exact(c2[ni][1] + b1)),
                                     f2tf_f(gelu_exact(c2[ni][3] + b1)));
    }
    __syncthreads();

    float c3[4] = {};
    #pragma unroll
    for (int ks = 0; ks < 32; ks++) {
        float4 a = reinterpret_cast<const float4*>(sT2)[(mw * 32 + ks) * 32 + lane];
        float2 bb = reinterpret_cast<const float2*>(sf3)[(nw * 32 + ks) * 32 + lane];
        mma_tf32(c3, a, bb);
    }

    const int col = nw * 8 + 2 * tg;
    const long rlo = r0 + mw * 16 + g, rhi = rlo + 8;
    const float b0 = fb3[col], b1 = fb3[col + 1];
    out[rlo * MD + col]     += c3[0] + b0;
    out[rlo * MD + col + 1] += c3[1] + b1;
    out[rhi * MD + col]     += c3[2] + b0;
    out[rhi * MD + col + 1] += c3[3] + b1;
}

extern "C" void kernel_launch(void* const* d_in, const int* in_sizes, int n_in,
                              void* d_out, int out_size) {
    const float* x   = (const float*)d_in[0];
    const float* psi = (const float*)d_in[1];
    const float* dw  = (const float*)d_in[2];
    const float* db  = (const float*)d_in[3];
    const float* hw1 = (const float*)d_in[4];
    const float* hb1 = (const float*)d_in[5];
    const float* hw2 = (const float*)d_in[6];
    const float* hb2 = (const float*)d_in[7];
    const float* fw1 = (const float*)d_in[8];
    const float* fb1 = (const float*)d_in[9];
    const float* fw2 = (const float*)d_in[10];
    const float* fb2 = (const float*)d_in[11];
    const float* fw3 = (const float*)d_in[12];
    const float* fb3 = (const float*)d_in[13];
    float* out = (float*)d_out;

    const size_t smD = SMEM_D_F * sizeof(float);
    const size_t smF = SFN_F * sizeof(float);
    cudaFuncSetAttribute(disco_head_mma, cudaFuncAttributeMaxDynamicSharedMemorySize, (int)smD);
    cudaFuncSetAttribute(ffn_fused, cudaFuncAttributeMaxDynamicSharedMemorySize, (int)smF);

    prep_weffBh<<<H, 256>>>(dw, psi);
    prep_hw1h<<<(HW1H_U2 + 255) / 256, 256>>>(hw1);
    prep_small<<<(FW1B_F + FW3B_F + 255) / 256, 256>>>(fw1, fw3);
    prep_fw2B<<<FW2B_F / 256, 256>>>(fw2);
    disco_head_mma<<<dim3(W / TW, H, B), TAD, smD>>>(x, db, hb1, hw2, hb2, out);
    ffn_fused<<<(unsigned)(M_PIX / 64), 512, smF>>>(out, fb1, fb2, fb3, out);
}

// round 15
// speedup vs baseline: 1.3732x; 1.3732x over previous
#include <cuda_runtime.h>

namespace {
constexpr int B = 2, H = 128, W = 256, MD = 34, LD = 32;
constexpr int NH = 4, SH = 64, K = 25, P = 7, R = 3;
constexpr int FF1 = 512, FF2 = 256;
constexpr int PP = P * P; // 49
constexpr long M_PIX = (long)B * H * W; // 65536

// ---------------- disco config ----------------
constexpr int TW   = 32;
constexpr int PIX  = 8;
constexpr int NGRP = TW / PIX;
constexpr int TAD  = 256;           // 8 warps, 2 m16-tiles per warp
constexpr int XCOLS = TW + 2 * R;   // 38

constexpr int WEFFB4_N = 8 * 4 * 32;        // 1024 float4 per latitude (16 KB)
constexpr int HW1B4_N  = 4 * 4 * 4 * 32;    // 2048 float4 (32 KB)
constexpr int FW1B_F  = 64 * 5 * 32 * 2;     // 20480 (k padded 34->40)
constexpr int FW2B_F  = 16 * 32 * 4 * 32 * 2;// 131072
constexpr int FW3B_F  = 4 * 32 * 32 * 2;     // 8192

// disco smem (floats): sx(rounded) + sxc(exact center) + small
constexpr int OFF_SX   = 0;                         // 8512
constexpr int OFF_SXC  = OFF_SX + LD * P * XCOLS;   // 1024
constexpr int OFF_SDB  = OFF_SXC + LD * TW;         // 64
constexpr int OFF_HB1  = OFF_SDB + SH;              // 128
constexpr int OFF_HW2  = OFF_HB1 + NH * 32;         // 128
constexpr int OFF_HB2  = OFF_HW2 + NH * 32;         // 4
constexpr int SMEM_D_F = OFF_HB2 + NH;              // 9860 fl = 39.4 KB

__device__ __forceinline__ float gelu_exact(float v) {
    return 0.5f * v * (1.0f + erff(v * 0.70710678118654752440f));
}

__device__ __forceinline__ float f2tf_f(float f) {
    unsigned u;
    asm("cvt.rna.tf32.f32 %0, %1;" : "=r"(u) : "f"(f));
    return __uint_as_float(u);
}

__device__ __forceinline__ void mma_tf32(float c[4], const float4& a, const float2& b) {
    const unsigned* A = reinterpret_cast<const unsigned*>(&a);
    const unsigned* Bv = reinterpret_cast<const unsigned*>(&b);
    asm volatile(
        "mma.sync.aligned.m16n8k8.row.col.f32.tf32.tf32.f32 "
        "{%0,%1,%2,%3},{%4,%5,%6,%7},{%8,%9},{%0,%1,%2,%3};\n"
        : "+f"(c[0]), "+f"(c[1]), "+f"(c[2]), "+f"(c[3])
        : "r"(A[0]), "r"(A[1]), "r"(A[2]), "r"(A[3]), "r"(Bv[0]), "r"(Bv[1]));
}
} // namespace

// device-global scratch (no runtime allocation)
__device__ __align__(16) float4 g_weffB4[H * WEFFB4_N]; // paired k8 frags
__device__ __align__(16) float4 g_hw1B4[HW1B4_N];       // paired k8 frags
__device__ __align__(16) float g_fw1B[FW1B_F];
__device__ __align__(16) float g_fw2B[FW2B_F];
__device__ __align__(16) float g_fw3B[FW3B_F];

// =====================================================================
// prep: fold psi into disco_w per latitude -> paired-k8 B-frags (float4)
//   q = (nt*4+kp)*32+lane ; {frag(ks=2kp).x,.y, frag(ks=2kp+1).x,.y}
//   frag(ks) = {weff[ks*8+tg][s], weff[ks*8+tg+4][s]}, zero for p>=49
// =====================================================================
__global__ void prep_weffB4(const float* __restrict__ dw,
                            const float* __restrict__ psi) {
    const int h = blockIdx.x;
    for (int e = threadIdx.x; e < WEFFB4_N; e += blockDim.x) {
        int lane = e & 31; int t = e >> 5;
        int kp = t & 3, nt = t >> 2;
        int g = lane >> 2, tg = lane & 3;
        int s = nt * 8 + g;
        int pj[4] = { 16 * kp + tg, 16 * kp + tg + 4,
                      16 * kp + 8 + tg, 16 * kp + 12 + tg };
        float v[4];
        #pragma unroll
        for (int j = 0; j < 4; j++) {
            float acc = 0.f;
            if (pj[j] < PP) {
                #pragma unroll
                for (int k = 0; k < K; k++)
                    acc += dw[s * K + k] * psi[(k * H + h) * PP + pj[j]];
            }
            v[j] = f2tf_f(acc);
        }
        g_weffB4[h * WEFFB4_N + e] = make_float4(v[0], v[1], v[2], v[3]);
    }
}

// =====================================================================
// prep: hw1 -> paired-k8 B-frags (float4)
//   q = ((n*4+nt2)*4+kp)*32+lane
//   frag(ks) = {hw1[n][ks*8+tg][o], hw1[n][ks*8+tg+4][o]}
// =====================================================================
__global__ void prep_hw1B4(const float* __restrict__ hw1) {
    int e = blockIdx.x * blockDim.x + threadIdx.x;
    if (e >= HW1B4_N) return;
    int lane = e & 31; int t = e >> 5;
    int kp = t & 3; t >>= 2;
    int nt2 = t & 3; int n = t >> 2;
    int g = lane >> 2, tg = lane & 3;
    int o = nt2 * 8 + g;
    int s0 = 16 * kp + tg;
    g_hw1B4[e] = make_float4(
        f2tf_f(hw1[(n * SH + s0)      * 32 + o]),
        f2tf_f(hw1[(n * SH + s0 + 4)  * 32 + o]),
        f2tf_f(hw1[(n * SH + s0 + 8)  * 32 + o]),
        f2tf_f(hw1[(n * SH + s0 + 12) * 32 + o]));
}

// =====================================================================
// prep: fw1 / fw3 into tf32 B-frag layouts (FFN unchanged)
// =====================================================================
__global__ void prep_small(const float* __restrict__ fw1,
                           const float* __restrict__ fw3) {
    int e = blockIdx.x * blockDim.x + threadIdx.x;
    if (e < FW1B_F) {
        int half = e & 1, t = e >> 1;
        int lane = t & 31; t >>= 5;
        int ks = t % 5, nt = t / 5;
        int g = lane >> 2, tg = lane & 3;
        int k = ks * 8 + tg + 4 * half;
        int n = nt * 8 + g;
        g_fw1B[e] = (k < MD) ? f2tf_f(fw1[k * FF1 + n]) : 0.f;
        return;
    }
    e -= FW1B_F;
    if (e < FW3B_F) {
        int half = e & 1, t = e >> 1;
        int lane = t & 31; t >>= 5;
        int ks = t & 31, nt = t >> 5;
        int g = lane >> 2, tg = lane & 3;
        int k = ks * 8 + tg + 4 * half;
        int n = nt * 8 + g;
        g_fw3B[e] = f2tf_f(fw3[k * LD + n]);
    }
}

// =====================================================================
// prep: fw2 into per-chunk tf32 B-frag layout
// =====================================================================
__global__ void prep_fw2B(const float* __restrict__ fw2) {
    int e = blockIdx.x * blockDim.x + threadIdx.x;
    if (e >= FW2B_F) return;
    int kc = e >> 13, r = e & 8191;
    int half = r & 1; r >>= 1;
    int lane = r & 31; r >>= 5;
    int ks = r & 3; int nt = r >> 2;
    int g = lane >> 2, tg = lane & 3;
    int k = kc * 32 + ks * 8 + tg + 4 * half;
    int n = nt * 8 + g;
    g_fw2B[e] = f2tf_f(fw2[k * FF2 + n]);
}

// =====================================================================
// disco conv + head MLP + residual (tf32 mma, R13 dataflow).
// Weight fragments loaded as float4 (two k8 steps per LDG.128);
// phase-1 K padded to 64 with zero weights -> no a-side predication.
// =====================================================================
__global__ __launch_bounds__(TAD, 2) void disco_head_mma(
    const float* __restrict__ x,   const float* __restrict__ db,
    const float* __restrict__ hb1, const float* __restrict__ hw2,
    const float* __restrict__ hb2, float* __restrict__ out)
{
    extern __shared__ float sm[];
    float* sx   = sm + OFF_SX;
    float* sxc  = sm + OFF_SXC;
    float* sdb  = sm + OFF_SDB;
    float* shb1 = sm + OFF_HB1;
    float* shw2 = sm + OFF_HW2;
    float* shb2 = sm + OFF_HB2;

    const int tid = threadIdx.x;
    const int lane = tid & 31, mt = tid >> 5;
    const int g  = lane >> 2, tg = lane & 3;
    const int w0 = blockIdx.x * TW;
    const int h  = blockIdx.y;
    const int b  = blockIdx.z;

    if (tid < SH) sdb[tid] = db[tid];
    if (tid < NH * 32) { shb1[tid] = hb1[tid]; shw2[tid] = hw2[tid]; }
    if (tid < NH) shb2[tid] = hb2[tid];

    for (int i = tid; i < LD * P * XCOLS; i += TAD) {
        int ld = i & 31; int pos = i >> 5;
        int r = pos / XCOLS, c = pos % XCOLS;
        int lat = h + r - R; lat = lat < 0 ? 0 : (lat > H - 1 ? H - 1 : lat);
        int lon = (w0 + c - R + W) & (W - 1);
        float v = x[((b * H + lat) * W + lon) * MD + ld];
        sx[(ld * P + r) * XCOLS + c] = f2tf_f(v);
        if (r == R && c >= R && c < R + TW) sxc[ld * TW + (c - R)] = v;
    }
    for (int i = tid; i < TW * 2; i += TAD) {
        int px = i >> 1, j = i & 1;
        int gi = ((b * H + h) * W + (w0 + px)) * MD + LD + j;
        out[gi] = x[gi];
    }
    __syncthreads();

    const int nh  = mt >> 1;
    const int ldA = nh * 8 + 4 * (mt & 1);
    const int px  = g;
    const int base0 = (ldA + 0) * P * XCOLS;
    const int base1 = (ldA + 1) * P * XCOLS;
    const int base2 = (ldA + 2) * P * XCOLS;
    const int base3 = (ldA + 3) * P * XCOLS;

    // 8 k8 steps; p>=49 -> dummy offset 0 (weights there are zero)
    int roff0[8], roff1[8];
    #pragma unroll
    for (int ks = 0; ks < 8; ks++) {
        int p0 = ks * 8 + tg, p1 = p0 + 4;
        roff0[ks] = (p0 < PP) ? (p0 / 7) * XCOLS + (p0 % 7) : 0;
        roff1[ks] = (p1 < PP) ? (p1 / 7) * XCOLS + (p1 % 7) : 0;
    }

    const float4* swB4 = g_weffB4 + (long)h * WEFFB4_N;
    const float4* h1B4 = g_hw1B4;

    const int src0 = (lane & ~3) | (tg >> 1);
    const int src1 = src0 + 2;
    const bool odd = (tg & 1);

    for (int grp = 0; grp < NGRP; grp++) {
        const int cbase = grp * PIX + px;
        const int cb0 = base0 + cbase, cb1 = base1 + cbase;
        const int cb2 = base2 + cbase, cb3 = base3 + cbase;

        // phase 1: d = taps @ weff  (two m16 tiles, N=64, K=64)
        float c1[2][8][4] = {};
        #pragma unroll
        for (int kp = 0; kp < 4; kp++) {
            const int ka = 2 * kp, kb = 2 * kp + 1;
            float4 aA0, aA1, aB0, aB1;
            aA0.x = sx[cb0 + roff0[ka]]; aA0.y = sx[cb1 + roff0[ka]];
            aA0.z = sx[cb0 + roff1[ka]]; aA0.w = sx[cb1 + roff1[ka]];
            aA1.x = sx[cb2 + roff0[ka]]; aA1.y = sx[cb3 + roff0[ka]];
            aA1.z = sx[cb2 + roff1[ka]]; aA1.w = sx[cb3 + roff1[ka]];
            aB0.x = sx[cb0 + roff0[kb]]; aB0.y = sx[cb1 + roff0[kb]];
            aB0.z = sx[cb0 + roff1[kb]]; aB0.w = sx[cb1 + roff1[kb]];
            aB1.x = sx[cb2 + roff0[kb]]; aB1.y = sx[cb3 + roff0[kb]];
            aB1.z = sx[cb2 + roff1[kb]]; aB1.w = sx[cb3 + roff1[kb]];
            #pragma unroll
            for (int nt = 0; nt < 8; nt++) {
                const float4 wb = __ldg(&swB4[(nt * 4 + kp) * 32 + lane]);
                const float2 blo = make_float2(wb.x, wb.y);
                const float2 bhi = make_float2(wb.z, wb.w);
                mma_tf32(c1[0][nt], aA0, blo);
                mma_tf32(c1[1][nt], aA1, blo);
                mma_tf32(c1[0][nt], aB0, bhi);
                mma_tf32(c1[1][nt], aB1, bhi);
            }
        }

        // phase 2 fused: per ks-pair, bias+round+shuffle C->A frags, then
        // each hw1 float4 load carries two k8 fragments (feeds 4 MMAs).
        float c2[2][4][4] = {};
        #pragma unroll
        for (int kp = 0; kp < 4; kp++) {
            float4 af[2][2];   // [tile][which ks of the pair]
            #pragma unroll
            for (int half = 0; half < 2; half++) {
                const int ks = 2 * kp + half;
                const int scol = ks * 8 + 2 * tg;
                const float b0 = sdb[scol], b1 = sdb[scol + 1];
                #pragma unroll
                for (int t = 0; t < 2; t++) {
                    const float y0 = f2tf_f(c1[t][ks][0] + b0);
                    const float y1 = f2tf_f(c1[t][ks][1] + b1);
                    const float y2 = f2tf_f(c1[t][ks][2] + b0);
                    const float y3 = f2tf_f(c1[t][ks][3] + b1);
                    const float u0 = __shfl_sync(0xffffffffu, y0, src0);
                    const float u1 = __shfl_sync(0xffffffffu, y1, src0);
                    const float u2 = __shfl_sync(0xffffffffu, y2, src0);
                    const float u3 = __shfl_sync(0xffffffffu, y3, src0);
                    const float v0 = __shfl_sync(0xffffffffu, y0, src1);
                    const float v1 = __shfl_sync(0xffffffffu, y1, src1);
                    const float v2 = __shfl_sync(0xffffffffu, y2, src1);
                    const float v3 = __shfl_sync(0xffffffffu, y3, src1);
                    af[t][half].x = odd ? u1 : u0;
                    af[t][half].y = odd ? u3 : u2;
                    af[t][half].z = odd ? v1 : v0;
                    af[t][half].w = odd ? v3 : v2;
                }
            }
            #pragma unroll
            for (int nt2 = 0; nt2 < 4; nt2++) {
                const float4 wb = __ldg(&h1B4[((nh * 4 + nt2) * 4 + kp) * 32 + lane]);
                const float2 blo = make_float2(wb.x, wb.y);
                const float2 bhi = make_float2(wb.z, wb.w);
                mma_tf32(c2[0][nt2], af[0][0], blo);
                mma_tf32(c2[1][nt2], af[1][0], blo);
                mma_tf32(c2[0][nt2], af[0][1], bhi);
                mma_tf32(c2[1][nt2], af[1][1], bhi);
            }
        }

        // epilogue: gelu + hw2 dot + lane reduce + residual (fp32 path)
        #pragma unroll
        for (int t = 0; t < 2; t++) {
            float part0 = 0.f, part1 = 0.f;
            #pragma unroll
            for (int nt2 = 0; nt2 < 4; nt2++) {
                const int o0 = nt2 * 8 + 2 * tg, o1 = o0 + 1;
                const float w0v = shw2[nh * 32 + o0], w1v = shw2[nh * 32 + o1];
                const float bb0 = shb1[nh * 32 + o0], bb1 = shb1[nh * 32 + o1];
                part0 += gelu_exact(c2[t][nt2][0] + bb0) * w0v
                       + gelu_exact(c2[t][nt2][1] + bb1) * w1v;
                part1 += gelu_exact(c2[t][nt2][2] + bb0) * w0v
                       + gelu_exact(c2[t][nt2][3] + bb1) * w1v;
            }
            part0 += __shfl_xor_sync(0xffffffffu, part0, 1);
            part0 += __shfl_xor_sync(0xffffffffu, part0, 2);
            part1 += __shfl_xor_sync(0xffffffffu, part1, 1);
            part1 += __shfl_xor_sync(0xffffffffu, part1, 2);
            if (tg == 0) {
                const int ld0 = ldA + 2 * t, ld1 = ld0 + 1;
                const int pxg = grp * PIX + px;
                const float v0 = part0 + shb2[nh] + sxc[ld0 * TW + pxg];
                const float v1 = part1 + shb2[nh] + sxc[ld1 * TW + pxg];
                const long o = ((long)(b * H + h) * W + w0 + pxg) * MD;
                out[o + ld0] = v0;
                out[o + ld1] = v1;
            }
        }
    }
}

// =====================================================================
// FFN fully fused (tf32, byte-for-byte R13)
// =====================================================================
namespace {
constexpr int FB_BUF  = 10240;                 // 2048 t1c + 8192 fw2
constexpr int FST2_F  = 4 * 32 * 32 * 4;       // 16384
constexpr int FSF3    = FST2_F;                // sf3 offset
constexpr int FFB1    = 24576;                 // fb1 offset
constexpr int SFN_F   = FFB1 + FF1;            // 25088 floats = 100.4 KB
}
__global__ __launch_bounds__(512) void ffn_fused(
    const float* __restrict__ xin, const float* __restrict__ fb1,
    const float* __restrict__ fb2, const float* __restrict__ fb3,
    float* __restrict__ out)
{
    extern __shared__ float sm[];
    float* sfb1 = sm + FFB1;
    const int tid = threadIdx.x, lane = tid & 31, w = tid >> 5;
    const int mw = w >> 2, nw = w & 3;
    const int g = lane >> 2, tg = lane & 3;
    const long r0 = (long)blockIdx.x * 64;

    sfb1[tid] = fb1[tid];

    {
        const int r = tid >> 3, rr7 = r & 7, rhi = (r >> 3) & 1, mt = r >> 4;
        const int kb = (tid & 7) * 5;
        #pragma unroll
        for (int j = 0; j < 5; j++) {
            const int k = kb + j;
            const float v = (k < MD) ? f2tf_f(xin[(r0 + r) * MD + k]) : 0.f;
            sm[((mt * 5 + (k >> 3)) * 32 + rr7 * 4 + (k & 3)) * 4
               + rhi + (((k >> 2) & 1) << 1)] = v;
        }
    }
    __syncthreads();
    float4 xfrag[5];
    #pragma unroll
    for (int ks = 0; ks < 5; ks++)
        xfrag[ks] = reinterpret_cast<const float4*>(sm)[(mw * 5 + ks) * 32 + lane];
    __syncthreads();

    float c2[8][4] = {};
    const float2* fw1b2 = reinterpret_cast<const float2*>(g_fw1B);
    const float4* fw2v4 = reinterpret_cast<const float4*>(g_fw2B);

    for (int kc = 0; kc < 16; kc++) {
        float* buf  = sm + (kc & 1) * FB_BUF;
        float* st1c = buf;
        float* sB   = buf + 2048;

        {
            float4* dst = reinterpret_cast<float4*>(sB);
            #pragma unroll
            for (int i = 0; i < 4; i++)
                dst[tid + i * 512] = fw2v4[kc * 2048 + tid + i * 512];
        }

        float c1[4] = {};
        #pragma unroll
        for (int ks = 0; ks < 5; ks++) {
            float2 bb = __ldg(&fw1b2[(((kc * 4 + nw) * 5) + ks) * 32 + lane]);
            mma_tf32(c1, xfrag[ks], bb);
        }
        {
            const int n = kc * 32 + nw * 8 + 2 * tg;
            const float b0 = sfb1[n], b1 = sfb1[n + 1];
            const int kk0 = 2 * tg, kk1 = kk0 + 1;
            const int i0 = mw * 512 + (nw * 32 + g * 4 + (kk0 & 3)) * 4 + ((kk0 >> 2) << 1);
            const int i1 = mw * 512 + (nw * 32 + g * 4 + (kk1 & 3)) * 4 + ((kk1 >> 2) << 1);
            *reinterpret_cast<float2*>(st1c + i0) =
                make_float2(f2tf_f(gelu_exact(c1[0] + b0)),
                            f2tf_f(gelu_exact(c1[2] + b0)));
            *reinterpret_cast<float2*>(st1c + i1) =
                make_float2(f2tf_f(gelu_exact(c1[1] + b1)),
                            f2tf_f(gelu_exact(c1[3] + b1)));
        }
        __syncthreads();

        #pragma unroll
        for (int ks = 0; ks < 4; ks++) {
            float4 a = reinterpret_cast<const float4*>(st1c)[(mw * 4 + ks) * 32 + lane];
            #pragma unroll
            for (int ni = 0; ni < 8; ni++) {
                float2 bb = reinterpret_cast<const float2*>(sB)[((nw * 8 + ni) * 4 + ks) * 32 + lane];
                mma_tf32(c2[ni], a, bb);
            }
        }
    }
    __syncthreads();

    float* sT2 = sm;
    float* sf3 = sm + FSF3;
    {
        const float4* src = reinterpret_cast<const float4*>(g_fw3B);
        float4* dst = reinterpret_cast<float4*>(sf3);
        #pragma unroll
        for (int i = 0; i < 4; i++) dst[tid + i * 512] = src[tid + i * 512];
    }
    float2* sT2v2 = reinterpret_cast<float2*>(sT2);
    #pragma unroll
    for (int ni = 0; ni < 8; ni++) {
        const int nt = nw * 8 + ni;
        const int n2 = nt * 8 + 2 * tg;
        const int kk0 = n2 & 7, kk1 = kk0 + 1;
        const int base = (mw * 32 + nt) * 32;
        const int rgA = ((kk0 >> 2) & 1) << 1;
        const int i0 = (base + g * 4 + (kk0 & 3)) * 4 + rgA;
        const int i1 = (base + g * 4 + (kk1 & 3)) * 4 + rgA;
        const float b0 = fb2[n2], b1 = fb2[n2 + 1];
        sT2v2[i0 >> 1] = make_float2(f2tf_f(gelu_exact(c2[ni][0] + b0)),
                                     f2tf_f(gelu_exact(c2[ni][2] + b0)));
        sT2v2[i1 >> 1] = make_float2(f2tf_f(gelu_exact(c2[ni][1] + b1)),
                                     f2tf_f(gelu_exact(c2[ni][3] + b1)));
    }
    __syncthreads();

    float c3[4] = {};
    #pragma unroll
    for (int ks = 0; ks < 32; ks++) {
        float4 a = reinterpret_cast<const float4*>(sT2)[(mw * 32 + ks) * 32 + lane];
        float2 bb = reinterpret_cast<const float2*>(sf3)[(nw * 32 + ks) * 32 + lane];
        mma_tf32(c3, a, bb);
    }

    const int col = nw * 8 + 2 * tg;
    const long rlo = r0 + mw * 16 + g, rhi = rlo + 8;
    const float b0 = fb3[col], b1 = fb3[col + 1];
    out[rlo * MD + col]     += c3[0] + b0;
    out[rlo * MD + col + 1] += c3[1] + b1;
    out[rhi * MD + col]     += c3[2] + b0;
    out[rhi * MD + col + 1] += c3[3] + b1;
}

extern "C" void kernel_launch(void* const* d_in, const int* in_sizes, int n_in,
                              void* d_out, int out_size) {
    const float* x   = (const float*)d_in[0];
    const float* psi = (const float*)d_in[1];
    const float* dw  = (const float*)d_in[2];
    const float* db  = (const float*)d_in[3];
    const float* hw1 = (const float*)d_in[4];
    const float* hb1 = (const float*)d_in[5];
    const float* hw2 = (const float*)d_in[6];
    const float* hb2 = (const float*)d_in[7];
    const float* fw1 = (const float*)d_in[8];
    const float* fb1 = (const float*)d_in[9];
    const float* fw2 = (const float*)d_in[10];
    const float* fb2 = (const float*)d_in[11];
    const float* fw3 = (const float*)d_in[12];
    const float* fb3 = (const float*)d_in[13];
    float* out = (float*)d_out;

    const size_t smD = SMEM_D_F * sizeof(float);
    const size_t smF = SFN_F * sizeof(float);
    cudaFuncSetAttribute(disco_head_mma, cudaFuncAttributeMaxDynamicSharedMemorySize, (int)smD);
    cudaFuncSetAttribute(ffn_fused, cudaFuncAttributeMaxDynamicSharedMemorySize, (int)smF);

    prep_weffB4<<<H, 256>>>(dw, psi);
    prep_hw1B4<<<(HW1B4_N + 255) / 256, 256>>>(hw1);
    prep_small<<<(FW1B_F + FW3B_F + 255) / 256, 256>>>(fw1, fw3);
    prep_fw2B<<<FW2B_F / 256, 256>>>(fw2);
    disco_head_mma<<<dim3(W / TW, H, B), TAD, smD>>>(x, db, hb1, hw2, hb2, out);
    ffn_fused<<<(unsigned)(M_PIX / 64), 512, smF>>>(out, fb1, fb2, fb3, out);
}